// round 1
// baseline (speedup 1.0000x reference)
#include <cuda_runtime.h>
#include <math.h>

#define NBLK   148
#define NTHR   256
#define NW     (NTHR / 32)
#define HID    512
#define TENC   16384
#define NVOCAB 31
#define MAXLEN 100
#define EOSI   29
#define PADV   30.0f
#define ROWS_PB ((TENC + NBLK - 1) / NBLK)   // 111

// ---------------- device scratch (no allocations allowed) ----------------
__device__ __align__(16) float g_y[HID];
__device__ __align__(16) float g_h[2][HID];
__device__ float g_psum[NBLK];
__device__ __align__(16) float g_psummary[NBLK][HID];
__device__ __align__(16) float g_exp[TENC];
__device__ unsigned int g_bar_count = 0;
__device__ volatile unsigned int g_bar_gen = 0;

// ---------------- grid barrier (sense-reversing) ----------------
__device__ __forceinline__ void grid_barrier() {
    __syncthreads();
    if (threadIdx.x == 0) {
        __threadfence();
        unsigned int gen = g_bar_gen;
        if (atomicAdd(&g_bar_count, 1u) == (unsigned)(NBLK - 1)) {
            g_bar_count = 0;
            __threadfence();
            g_bar_gen = gen + 1;
        } else {
            while (g_bar_gen == gen) { }
            __threadfence();
        }
    }
    __syncthreads();
}

__device__ __forceinline__ float warp_sum(float v) {
    #pragma unroll
    for (int o = 16; o; o >>= 1) v += __shfl_down_sync(0xffffffffu, v, o);
    return v;
}

__global__ void __launch_bounds__(NTHR, 1)
decoder_kernel(const float* __restrict__ enc,     // [TENC, 1024] keys|values
               const float* __restrict__ embed,   // [31, 512]
               const float* __restrict__ w_ih,    // [1536, 512]
               const float* __restrict__ w_hh,    // [1536, 512]
               const float* __restrict__ b_ih,    // [1536]
               const float* __restrict__ b_hh,    // [1536]
               const float* __restrict__ w_out,   // [31, 1024]
               const float* __restrict__ b_out,   // [31]
               float* __restrict__ out)
{
    const int tid  = threadIdx.x;
    const int blk  = blockIdx.x;
    const int wid  = tid >> 5;
    const int lane = tid & 31;

    __shared__ __align__(16) float s_h[HID];
    __shared__ __align__(16) float s_acc[HID];
    __shared__ __align__(16) float s_cat[2 * HID];
    __shared__ float s_logit[NVOCAB];
    __shared__ float s_red[NW];
    __shared__ float s_total;
    __shared__ int   s_best;

    float* out_logits = out;                        // [100, 31]
    float* out_len    = out + MAXLEN * NVOCAB;      // [1]
    float* out_attn   = out + MAXLEN * NVOCAB + 1;  // [100, 16384]

    // ---- init: y0 = embed[EOS], h0 = 0 ----
    if (blk == 0) {
        for (int d = tid; d < HID; d += NTHR) {
            g_y[d]    = embed[EOSI * HID + d];
            g_h[0][d] = 0.0f;
        }
    }
    int eos_step = MAXLEN;   // meaningful only on blk0/tid0

    grid_barrier();

    const int t0 = blk * ROWS_PB;
    const int t1 = (t0 + ROWS_PB < TENC) ? (t0 + ROWS_PB) : TENC;
    const float scale = 0.04419417382415922f;   // 1/sqrt(512)

    for (int s = 0; s < MAXLEN; ++s) {
        const float* __restrict__ h_old = g_h[s & 1];
        float*       __restrict__ h_new = g_h[(s + 1) & 1];

        // ================= Phase 1: GRU cell =================
        // one warp per hidden unit j: six 512-length dot products
        {
            int j = blk * NW + wid;      // global warp id -> unit
            if (j < HID) {
                const float* wr = w_ih + (size_t)j * HID;
                const float* wz = w_ih + (size_t)(j + HID) * HID;
                const float* wn = w_ih + (size_t)(j + 2 * HID) * HID;
                const float* ur = w_hh + (size_t)j * HID;
                const float* uz = w_hh + (size_t)(j + HID) * HID;
                const float* un = w_hh + (size_t)(j + 2 * HID) * HID;
                float a0 = 0, a1 = 0, a2 = 0, a3 = 0, a4 = 0, a5 = 0;
                #pragma unroll
                for (int m = 0; m < 4; ++m) {
                    int c = lane * 4 + m * 128;
                    float4 y4 = *(const float4*)(g_y + c);
                    float4 h4 = *(const float4*)(h_old + c);
                    float4 w0 = *(const float4*)(wr + c);
                    float4 w1 = *(const float4*)(wz + c);
                    float4 w2 = *(const float4*)(wn + c);
                    float4 u0 = *(const float4*)(ur + c);
                    float4 u1 = *(const float4*)(uz + c);
                    float4 u2 = *(const float4*)(un + c);
                    a0 += y4.x*w0.x + y4.y*w0.y + y4.z*w0.z + y4.w*w0.w;
                    a1 += y4.x*w1.x + y4.y*w1.y + y4.z*w1.z + y4.w*w1.w;
                    a2 += y4.x*w2.x + y4.y*w2.y + y4.z*w2.z + y4.w*w2.w;
                    a3 += h4.x*u0.x + h4.y*u0.y + h4.z*u0.z + h4.w*u0.w;
                    a4 += h4.x*u1.x + h4.y*u1.y + h4.z*u1.z + h4.w*u1.w;
                    a5 += h4.x*u2.x + h4.y*u2.y + h4.z*u2.z + h4.w*u2.w;
                }
                a0 = warp_sum(a0); a1 = warp_sum(a1); a2 = warp_sum(a2);
                a3 = warp_sum(a3); a4 = warp_sum(a4); a5 = warp_sum(a5);
                if (lane == 0) {
                    float gxr = a0 + b_ih[j];
                    float gxz = a1 + b_ih[j + HID];
                    float gxn = a2 + b_ih[j + 2 * HID];
                    float ghr = a3 + b_hh[j];
                    float ghz = a4 + b_hh[j + HID];
                    float ghn = a5 + b_hh[j + 2 * HID];
                    float r = 1.0f / (1.0f + expf(-(gxr + ghr)));
                    float z = 1.0f / (1.0f + expf(-(gxz + ghz)));
                    float n = tanhf(gxn + r * ghn);
                    h_new[j] = (1.0f - z) * n + z * h_old[j];
                }
            }
        }
        grid_barrier();

        // ======= Phase 2: scores + exp + partial softmax-sum + partial summary =======
        for (int d = tid; d < HID; d += NTHR) { s_h[d] = h_new[d]; s_acc[d] = 0.0f; }
        __syncthreads();

        float4 acc0 = {0,0,0,0}, acc1 = {0,0,0,0}, acc2 = {0,0,0,0}, acc3 = {0,0,0,0};
        float esum = 0.0f;

        for (int t = t0 + wid; t < t1; t += NW) {
            const float* row = enc + (size_t)t * (2 * HID);
            float dot = 0.0f;
            bool  ok  = false;
            float4 v0, v1, v2, v3;
            {
                int c;
                c = lane * 4 + 0 * 128;
                { float4 k4 = *(const float4*)(row + c); float4 hh = *(const float4*)(s_h + c);
                  dot += k4.x*hh.x + k4.y*hh.y + k4.z*hh.z + k4.w*hh.w;
                  ok = ok || (k4.x != PADV) || (k4.y != PADV) || (k4.z != PADV) || (k4.w != PADV);
                  v0 = *(const float4*)(row + HID + c); }
                c = lane * 4 + 1 * 128;
                { float4 k4 = *(const float4*)(row + c); float4 hh = *(const float4*)(s_h + c);
                  dot += k4.x*hh.x + k4.y*hh.y + k4.z*hh.z + k4.w*hh.w;
                  ok = ok || (k4.x != PADV) || (k4.y != PADV) || (k4.z != PADV) || (k4.w != PADV);
                  v1 = *(const float4*)(row + HID + c); }
                c = lane * 4 + 2 * 128;
                { float4 k4 = *(const float4*)(row + c); float4 hh = *(const float4*)(s_h + c);
                  dot += k4.x*hh.x + k4.y*hh.y + k4.z*hh.z + k4.w*hh.w;
                  ok = ok || (k4.x != PADV) || (k4.y != PADV) || (k4.z != PADV) || (k4.w != PADV);
                  v2 = *(const float4*)(row + HID + c); }
                c = lane * 4 + 3 * 128;
                { float4 k4 = *(const float4*)(row + c); float4 hh = *(const float4*)(s_h + c);
                  dot += k4.x*hh.x + k4.y*hh.y + k4.z*hh.z + k4.w*hh.w;
                  ok = ok || (k4.x != PADV) || (k4.y != PADV) || (k4.z != PADV) || (k4.w != PADV);
                  v3 = *(const float4*)(row + HID + c); }
            }
            dot = warp_sum(dot);
            ok  = __any_sync(0xffffffffu, ok);
            dot = __shfl_sync(0xffffffffu, dot, 0);
            float e = ok ? expf(dot * scale) : 0.0f;   // no max-sub needed: |score| <= ~23
            if (lane == 0) { g_exp[t] = e; esum += e; }
            acc0.x += e*v0.x; acc0.y += e*v0.y; acc0.z += e*v0.z; acc0.w += e*v0.w;
            acc1.x += e*v1.x; acc1.y += e*v1.y; acc1.z += e*v1.z; acc1.w += e*v1.w;
            acc2.x += e*v2.x; acc2.y += e*v2.y; acc2.z += e*v2.z; acc2.w += e*v2.w;
            acc3.x += e*v3.x; acc3.y += e*v3.y; acc3.z += e*v3.z; acc3.w += e*v3.w;
        }
        {
            int c = lane * 4;
            atomicAdd(&s_acc[c + 0],       acc0.x); atomicAdd(&s_acc[c + 1],       acc0.y);
            atomicAdd(&s_acc[c + 2],       acc0.z); atomicAdd(&s_acc[c + 3],       acc0.w);
            atomicAdd(&s_acc[c + 128 + 0], acc1.x); atomicAdd(&s_acc[c + 128 + 1], acc1.y);
            atomicAdd(&s_acc[c + 128 + 2], acc1.z); atomicAdd(&s_acc[c + 128 + 3], acc1.w);
            atomicAdd(&s_acc[c + 256 + 0], acc2.x); atomicAdd(&s_acc[c + 256 + 1], acc2.y);
            atomicAdd(&s_acc[c + 256 + 2], acc2.z); atomicAdd(&s_acc[c + 256 + 3], acc2.w);
            atomicAdd(&s_acc[c + 384 + 0], acc3.x); atomicAdd(&s_acc[c + 384 + 1], acc3.y);
            atomicAdd(&s_acc[c + 384 + 2], acc3.z); atomicAdd(&s_acc[c + 384 + 3], acc3.w);
        }
        if (lane == 0) s_red[wid] = esum;
        __syncthreads();
        if (tid == 0) {
            float tot = 0.0f;
            #pragma unroll
            for (int w = 0; w < NW; ++w) tot += s_red[w];
            g_psum[blk] = tot;
        }
        for (int d = tid; d < HID; d += NTHR) g_psummary[blk][d] = s_acc[d];
        grid_barrier();

        // ================= Phase 3: reduce + attn out + logits + argmax + embed =================
        {
            float v = (tid < NBLK) ? g_psum[tid] : 0.0f;
            v = warp_sum(v);
            if (lane == 0) s_red[wid] = v;
            __syncthreads();
            if (tid == 0) {
                float tot = 0.0f;
                #pragma unroll
                for (int w = 0; w < NW; ++w) tot += s_red[w];
                s_total = tot;
            }
            __syncthreads();
        }
        const float inv_total = 1.0f / s_total;

        // every block writes the normalized attention for its own t-range
        for (int t = t0 + tid; t < t1; t += NTHR)
            out_attn[(size_t)s * TENC + t] = g_exp[t] * inv_total;

        if (blk == 0) {
            // reduce summary across 148 partials; build [summary | h_new]
            for (int d = tid; d < HID; d += NTHR) {
                float sum = 0.0f;
                for (int b = 0; b < NBLK; ++b) sum += g_psummary[b][d];
                s_cat[d] = sum * inv_total;
                s_cat[HID + d] = s_h[d];
            }
            __syncthreads();
            // logits: one warp per vocab unit, 1024-length dots
            for (int v = wid; v < NVOCAB; v += NW) {
                const float* wrow = w_out + (size_t)v * (2 * HID);
                float dot = 0.0f;
                #pragma unroll
                for (int m = 0; m < 8; ++m) {
                    int c = lane * 4 + m * 128;
                    float4 w4 = *(const float4*)(wrow + c);
                    float4 x4 = *(const float4*)(s_cat + c);
                    dot += w4.x*x4.x + w4.y*x4.y + w4.z*x4.z + w4.w*x4.w;
                }
                dot = warp_sum(dot);
                if (lane == 0) {
                    dot += b_out[v];
                    s_logit[v] = dot;
                    out_logits[s * NVOCAB + v] = dot;
                }
            }
            __syncthreads();
            if (tid == 0) {
                int best = 0; float bv = s_logit[0];
                #pragma unroll
                for (int v = 1; v < NVOCAB; ++v)
                    if (s_logit[v] > bv) { bv = s_logit[v]; best = v; }
                s_best = best;
                if (best == EOSI && eos_step == MAXLEN) eos_step = s;
            }
            __syncthreads();
            int best = s_best;
            for (int d = tid; d < HID; d += NTHR)
                g_y[d] = embed[best * HID + d];
        }
        grid_barrier();
    }

    if (blk == 0 && tid == 0) out_len[0] = (float)eos_step;
}

extern "C" void kernel_launch(void* const* d_in, const int* in_sizes, int n_in,
                              void* d_out, int out_size) {
    const float* enc   = (const float*)d_in[0];   // encoding [1,16384,1024]
    // d_in[1] = encoding_lens (int64) -- unused by the reference math
    const float* embed = (const float*)d_in[2];
    const float* w_ih  = (const float*)d_in[3];
    const float* w_hh  = (const float*)d_in[4];
    const float* b_ih  = (const float*)d_in[5];
    const float* b_hh  = (const float*)d_in[6];
    const float* w_out = (const float*)d_in[7];
    const float* b_out = (const float*)d_in[8];
    (void)in_sizes; (void)n_in; (void)out_size;

    decoder_kernel<<<NBLK, NTHR>>>(enc, embed, w_ih, w_hh, b_ih, b_hh,
                                   w_out, b_out, (float*)d_out);
}

// round 2
// speedup vs baseline: 1.4726x; 1.4726x over previous
#include <cuda_runtime.h>
#include <math.h>

#define NBLK   148
#define NTHR   512
#define NW     (NTHR / 32)        // 16 warps
#define HID    512
#define TENC   16384
#define NVOCAB 31
#define MAXLEN 100
#define EOSI   29
#define PADV   30.0f

// ---------------- device scratch (statics: zero-initialized at load) ----------------
__device__ __align__(16) float g_h[2][HID];          // hidden state double buffer
__device__ __align__(16) float g_gh[3][HID];         // precomputed w_hh@h + b_hh (r,z,n)
__device__ __align__(16) float g_sumv[2][HID];       // attention summary accumulators
__device__ float g_tot[2];                           // softmax denominators
__device__ __align__(16) float g_gx[NVOCAB][3 * HID];// precomputed w_ih@embed[v] + b_ih
__device__ volatile int g_arrive[NBLK];
__device__ volatile int g_release;

__device__ __forceinline__ float warp_allsum(float v) {
    #pragma unroll
    for (int o = 16; o; o >>= 1) v += __shfl_xor_sync(0xffffffffu, v, o);
    return v;
}

__global__ void __launch_bounds__(NTHR, 1)
decoder_kernel(const float* __restrict__ enc,     // [TENC, 1024] keys|values
               const float* __restrict__ embed,   // [31, 512]
               const float* __restrict__ w_ih,    // [1536, 512]
               const float* __restrict__ w_hh,    // [1536, 512]
               const float* __restrict__ b_ih,    // [1536]
               const float* __restrict__ b_hh,    // [1536]
               const float* __restrict__ w_out,   // [31, 1024]
               const float* __restrict__ b_out,   // [31]
               float* __restrict__ out)
{
    const int tid  = threadIdx.x;
    const int blk  = blockIdx.x;
    const int wid  = tid >> 5;
    const int lane = tid & 31;
    const int base = lane * 4;

    __shared__ __align__(16) float s_h[HID];
    __shared__ __align__(16) float s_acc[HID];
    __shared__ __align__(16) float s_cat[2 * HID];
    __shared__ float s_exp[128];
    __shared__ float s_logit[NVOCAB];
    __shared__ float s_red[NW];
    __shared__ float s_total;
    __shared__ int   s_best;

    float* out_logits = out;                        // [100, 31]
    float* out_len    = out + MAXLEN * NVOCAB;      // [1]
    float* out_attn   = out + MAXLEN * NVOCAB + 1;  // [100, 16384]

    // persistent epoch (continues across launches; flags stay consistent)
    int ep = g_release;

    // ---------------- grid barrier (flag array + release broadcast) --------------
    auto grid_barrier = [&]() {
        ep++;
        __syncthreads();
        __threadfence();
        if (blk == 0) {
            for (int i = tid; i < NBLK; i += NTHR)
                if (i > 0) { while (g_arrive[i] < ep) { } }
            __threadfence();
            __syncthreads();
            if (tid == 0) g_release = ep;
        } else {
            if (tid == 0) {
                g_arrive[blk] = ep;
                while (g_release < ep) { }
                __threadfence();
            }
        }
        __syncthreads();
    };

    // ---------------- init ----------------
    if (blk == 0) {
        for (int d = tid; d < HID; d += NTHR) {
            g_h[0][d] = 0.0f;
            g_gh[0][d] = b_hh[d];              // h0 = 0 -> gh = b_hh
            g_gh[1][d] = b_hh[d + HID];
            g_gh[2][d] = b_hh[d + 2 * HID];
            g_sumv[0][d] = 0.0f;
            g_sumv[1][d] = 0.0f;
        }
        if (tid == 0) { g_tot[0] = 0.0f; g_tot[1] = 0.0f; s_best = EOSI; }
    }
    // gx_table: gx[v][u] = w_ih[u] . embed[v] + b_ih[u]   (31*1536 rows over all warps)
    {
        const int gw = blk * NW + wid;
        for (int r = gw; r < NVOCAB * 3 * HID; r += NBLK * NW) {
            const int v = r / (3 * HID);
            const int u = r - v * (3 * HID);
            const float* wrow = w_ih + (size_t)u * HID;
            const float* erow = embed + (size_t)v * HID;
            float a = 0.0f;
            #pragma unroll
            for (int m = 0; m < 4; ++m) {
                int c = base + m * 128;
                float4 w4 = *(const float4*)(wrow + c);
                float4 e4 = *(const float4*)(erow + c);
                a += w4.x * e4.x + w4.y * e4.y + w4.z * e4.z + w4.w * e4.w;
            }
            a = warp_allsum(a);
            if (lane == 0) g_gx[v][u] = a + b_ih[u];
        }
    }
    int eos_step = MAXLEN;   // tracked by blk0/tid0

    grid_barrier();

    // row partition: blk0 (GRU finish + logits) lighter, blks 1-31 (gh precompute) light
    int t0, t1;
    if (blk == 0)      { t0 = 0;                       t1 = 85; }
    else if (blk < 32) { t0 = 85 + (blk - 1) * 101;    t1 = t0 + 101; }
    else               { t0 = 3216 + (blk - 32) * 114; t1 = t0 + 114; if (t1 > TENC) t1 = TENC; }

    const float scale = 0.04419417382415922f;   // 1/sqrt(512)

    for (int s = 0; s < MAXLEN; ++s) {
        const int hold = s & 1;
        const int hnew = (s + 1) & 1;
        const int buf  = s & 1;
        const int nbuf = (s + 1) & 1;

        // ===== Phase 1': pointwise GRU finish (block 0 only; gh, gx precomputed) =====
        if (blk == 0) {
            const int best = s_best;
            const float* gx = g_gx[best];
            for (int j = tid; j < HID; j += NTHR) {
                float r = 1.0f / (1.0f + expf(-(gx[j]           + g_gh[0][j])));
                float z = 1.0f / (1.0f + expf(-(gx[j + HID]     + g_gh[1][j])));
                float n = tanhf(gx[j + 2 * HID] + r * g_gh[2][j]);
                g_h[hnew][j] = (1.0f - z) * n + z * g_h[hold][j];
            }
        }
        grid_barrier();   // barrier 1: h_new visible (+ zeroed buffers from prev phase3)

        // ===== Phase 2: attention partials (+ gh precompute on blocks 0-31) =====
        for (int d = tid; d < HID; d += NTHR) { s_h[d] = g_h[hnew][d]; s_acc[d] = 0.0f; }
        __syncthreads();

        float4 acc0 = {0,0,0,0}, acc1 = {0,0,0,0}, acc2 = {0,0,0,0}, acc3 = {0,0,0,0};
        float esum = 0.0f;

        for (int t = t0 + wid; t < t1; t += NW) {
            const float* __restrict__ row = enc + (size_t)t * (2 * HID);
            float dot = 0.0f;
            int   ok  = 0;
            float4 v0, v1, v2, v3;
            {
                float4 k4, h4;
                k4 = *(const float4*)(row + base);       h4 = *(const float4*)(s_h + base);
                dot += k4.x*h4.x + k4.y*h4.y + k4.z*h4.z + k4.w*h4.w;
                ok |= (k4.x != PADV) | (k4.y != PADV) | (k4.z != PADV) | (k4.w != PADV);
                v0 = *(const float4*)(row + HID + base);
                k4 = *(const float4*)(row + base + 128); h4 = *(const float4*)(s_h + base + 128);
                dot += k4.x*h4.x + k4.y*h4.y + k4.z*h4.z + k4.w*h4.w;
                ok |= (k4.x != PADV) | (k4.y != PADV) | (k4.z != PADV) | (k4.w != PADV);
                v1 = *(const float4*)(row + HID + base + 128);
                k4 = *(const float4*)(row + base + 256); h4 = *(const float4*)(s_h + base + 256);
                dot += k4.x*h4.x + k4.y*h4.y + k4.z*h4.z + k4.w*h4.w;
                ok |= (k4.x != PADV) | (k4.y != PADV) | (k4.z != PADV) | (k4.w != PADV);
                v2 = *(const float4*)(row + HID + base + 256);
                k4 = *(const float4*)(row + base + 384); h4 = *(const float4*)(s_h + base + 384);
                dot += k4.x*h4.x + k4.y*h4.y + k4.z*h4.z + k4.w*h4.w;
                ok |= (k4.x != PADV) | (k4.y != PADV) | (k4.z != PADV) | (k4.w != PADV);
                v3 = *(const float4*)(row + HID + base + 384);
            }
            dot = warp_allsum(dot);
            ok  = __any_sync(0xffffffffu, ok);
            float e = ok ? __expf(dot * scale) : 0.0f;   // |score| <= ~23: no max-sub needed
            if (lane == 0) { s_exp[t - t0] = e; esum += e; }
            acc0.x += e*v0.x; acc0.y += e*v0.y; acc0.z += e*v0.z; acc0.w += e*v0.w;
            acc1.x += e*v1.x; acc1.y += e*v1.y; acc1.z += e*v1.z; acc1.w += e*v1.w;
            acc2.x += e*v2.x; acc2.y += e*v2.y; acc2.z += e*v2.z; acc2.w += e*v2.w;
            acc3.x += e*v3.x; acc3.y += e*v3.y; acc3.z += e*v3.z; acc3.w += e*v3.w;
        }

        // gh precompute for NEXT step (blocks 0-31, one warp per hidden unit)
        if (blk < 32) {
            const int j = blk * NW + wid;
            const float* ur = w_hh + (size_t)j * HID;
            const float* uz = ur + (size_t)HID * HID;
            const float* un = uz + (size_t)HID * HID;
            float a3 = 0, a4 = 0, a5 = 0;
            #pragma unroll
            for (int m = 0; m < 4; ++m) {
                int c = base + m * 128;
                float4 h4 = *(const float4*)(s_h + c);
                float4 u0 = *(const float4*)(ur + c);
                float4 u1 = *(const float4*)(uz + c);
                float4 u2 = *(const float4*)(un + c);
                a3 += h4.x*u0.x + h4.y*u0.y + h4.z*u0.z + h4.w*u0.w;
                a4 += h4.x*u1.x + h4.y*u1.y + h4.z*u1.z + h4.w*u1.w;
                a5 += h4.x*u2.x + h4.y*u2.y + h4.z*u2.z + h4.w*u2.w;
            }
            a3 = warp_allsum(a3); a4 = warp_allsum(a4); a5 = warp_allsum(a5);
            if (lane == 0) {
                g_gh[0][j] = a3 + b_hh[j];
                g_gh[1][j] = a4 + b_hh[j + HID];
                g_gh[2][j] = a5 + b_hh[j + 2 * HID];
            }
        }

        // merge per-thread value accumulators into block accumulator
        atomicAdd(&s_acc[base + 0],       acc0.x); atomicAdd(&s_acc[base + 1],       acc0.y);
        atomicAdd(&s_acc[base + 2],       acc0.z); atomicAdd(&s_acc[base + 3],       acc0.w);
        atomicAdd(&s_acc[base + 128 + 0], acc1.x); atomicAdd(&s_acc[base + 128 + 1], acc1.y);
        atomicAdd(&s_acc[base + 128 + 2], acc1.z); atomicAdd(&s_acc[base + 128 + 3], acc1.w);
        atomicAdd(&s_acc[base + 256 + 0], acc2.x); atomicAdd(&s_acc[base + 256 + 1], acc2.y);
        atomicAdd(&s_acc[base + 256 + 2], acc2.z); atomicAdd(&s_acc[base + 256 + 3], acc2.w);
        atomicAdd(&s_acc[base + 384 + 0], acc3.x); atomicAdd(&s_acc[base + 384 + 1], acc3.y);
        atomicAdd(&s_acc[base + 384 + 2], acc3.z); atomicAdd(&s_acc[base + 384 + 3], acc3.w);
        if (lane == 0) s_red[wid] = esum;
        __syncthreads();
        if (tid == 0) {
            float tot = 0.0f;
            #pragma unroll
            for (int w = 0; w < NW; ++w) tot += s_red[w];
            atomicAdd(&g_tot[buf], tot);
        }
        for (int d = tid; d < HID; d += NTHR) atomicAdd(&g_sumv[buf][d], s_acc[d]);

        grid_barrier();   // barrier 2: partials complete

        // ===== Phase 3: normalize + outputs; block 0: logits/argmax =====
        if (tid == 0) s_total = g_tot[buf];
        __syncthreads();
        const float inv_total = 1.0f / s_total;

        for (int t = t0 + tid; t < t1; t += NTHR)
            out_attn[(size_t)s * TENC + t] = s_exp[t - t0] * inv_total;

        if (blk == 0) {
            for (int d = tid; d < HID; d += NTHR) {
                s_cat[d]       = g_sumv[buf][d] * inv_total;
                s_cat[HID + d] = s_h[d];
                g_sumv[nbuf][d] = 0.0f;          // zero next buffers for phase 2(s+1)
            }
            if (tid == 0) g_tot[nbuf] = 0.0f;
            __syncthreads();
            for (int v = wid; v < NVOCAB; v += NW) {
                const float* wrow = w_out + (size_t)v * (2 * HID);
                float dot = 0.0f;
                #pragma unroll
                for (int m = 0; m < 8; ++m) {
                    int c = base + m * 128;
                    float4 w4 = *(const float4*)(wrow + c);
                    float4 x4 = *(const float4*)(s_cat + c);
                    dot += w4.x*x4.x + w4.y*x4.y + w4.z*x4.z + w4.w*x4.w;
                }
                dot = warp_allsum(dot);
                if (lane == 0) {
                    dot += b_out[v];
                    s_logit[v] = dot;
                    out_logits[s * NVOCAB + v] = dot;
                }
            }
            __syncthreads();
            if (tid == 0) {
                int best = 0; float bv = s_logit[0];
                #pragma unroll
                for (int v = 1; v < NVOCAB; ++v)
                    if (s_logit[v] > bv) { bv = s_logit[v]; best = v; }
                s_best = best;
                if (best == EOSI && eos_step == MAXLEN) eos_step = s;
            }
            __syncthreads();   // s_best visible to phase 1' of next step
        }
    }

    if (blk == 0 && tid == 0) out_len[0] = (float)eos_step;
}

extern "C" void kernel_launch(void* const* d_in, const int* in_sizes, int n_in,
                              void* d_out, int out_size) {
    const float* enc   = (const float*)d_in[0];   // encoding [1,16384,1024]
    // d_in[1] = encoding_lens (int64) -- unused by the reference math
    const float* embed = (const float*)d_in[2];
    const float* w_ih  = (const float*)d_in[3];
    const float* w_hh  = (const float*)d_in[4];
    const float* b_ih  = (const float*)d_in[5];
    const float* b_hh  = (const float*)d_in[6];
    const float* w_out = (const float*)d_in[7];
    const float* b_out = (const float*)d_in[8];
    (void)in_sizes; (void)n_in; (void)out_size;

    decoder_kernel<<<NBLK, NTHR>>>(enc, embed, w_ih, w_hh, b_ih, b_hh,
                                   w_out, b_out, (float*)d_out);
}

// round 3
// speedup vs baseline: 1.6140x; 1.0960x over previous
#include <cuda_runtime.h>
#include <math.h>

#define NBLK   148
#define NTHR   512
#define NW     (NTHR / 32)        // 16 warps
#define HID    512
#define TENC   16384
#define NVOCAB 31
#define MAXLEN 100
#define EOSI   29
#define PADV   30.0f
#define NBUF   3

// ---------------- device scratch ----------------
__device__ __align__(16) float g_sumv[NBUF][HID];     // attention summary accumulators
__device__ float g_tot[NBUF];                         // softmax denominators
__device__ __align__(16) float g_gh[2][3][HID];       // w_hh@h + b_hh (r,z,n), double buffered
__device__ __align__(16) float g_gx[NVOCAB][3 * HID]; // w_ih@embed[v] + b_ih
__device__ volatile int g_arrive[NBLK];
__device__ volatile int g_release;

__device__ __forceinline__ float warp_allsum(float v) {
    #pragma unroll
    for (int o = 16; o; o >>= 1) v += __shfl_xor_sync(0xffffffffu, v, o);
    return v;
}

extern __shared__ float s_wout[];   // [31][1024] copy of w_out

__global__ void __launch_bounds__(NTHR, 1)
decoder_kernel(const float* __restrict__ enc,     // [TENC, 1024] keys|values
               const float* __restrict__ embed,   // [31, 512]
               const float* __restrict__ w_ih,    // [1536, 512]
               const float* __restrict__ w_hh,    // [1536, 512]
               const float* __restrict__ b_ih,    // [1536]
               const float* __restrict__ b_hh,    // [1536]
               const float* __restrict__ w_out,   // [31, 1024]
               const float* __restrict__ b_out,   // [31]
               float* __restrict__ out)
{
    const int tid  = threadIdx.x;
    const int blk  = blockIdx.x;
    const int wid  = tid >> 5;
    const int lane = tid & 31;
    const int base = lane * 4;

    __shared__ __align__(16) float s_hh[HID];       // local copy of h (per block)
    __shared__ __align__(16) float s_cat[2 * HID];
    __shared__ __align__(16) float s_acc[HID];
    __shared__ float s_exp[128];
    __shared__ float s_logit[NVOCAB];
    __shared__ float s_red[NW];
    __shared__ int   s_best;

    float* out_logits = out;                        // [100, 31]
    float* out_len    = out + MAXLEN * NVOCAB;      // [1]
    float* out_attn   = out + MAXLEN * NVOCAB + 1;  // [100, 16384]

    int ep = g_release;   // persistent epoch base (safe: publish is gated on all arrivals)

    auto grid_barrier = [&]() {
        ep++;
        __syncthreads();
        __threadfence();
        if (blk == 0) {
            for (int i = tid; i < NBLK; i += NTHR)
                if (i > 0) { while (g_arrive[i] < ep) { } }
            __threadfence();
            __syncthreads();
            if (tid == 0) g_release = ep;
        } else {
            if (tid == 0) {
                g_arrive[blk] = ep;
                while (g_release < ep) { }
                __threadfence();
            }
        }
        __syncthreads();
    };

    // ---------------- per-launch init ----------------
    // local state
    s_hh[tid] = 0.0f;                     // h0 = 0   (NTHR == HID)
    if (tid == 0) s_best = EOSI;          // y0 = embed[EOS]
    // w_out -> smem (one block-local copy)
    for (int i = tid; i < NVOCAB * 2 * HID; i += NTHR) s_wout[i] = w_out[i];
    // global buffers (block 0)
    if (blk == 0) {
        #pragma unroll
        for (int b = 0; b < NBUF; ++b) g_sumv[b][tid] = 0.0f;
        g_gh[0][0][tid] = b_hh[tid];
        g_gh[0][1][tid] = b_hh[tid + HID];
        g_gh[0][2][tid] = b_hh[tid + 2 * HID];
        if (tid == 0) { g_tot[0] = 0.0f; g_tot[1] = 0.0f; g_tot[2] = 0.0f; }
    }
    // gx table: gx[v][u] = w_ih[u] . embed[v] + b_ih[u]
    {
        const int gw = blk * NW + wid;
        for (int r = gw; r < NVOCAB * 3 * HID; r += NBLK * NW) {
            const int v = r / (3 * HID);
            const int u = r - v * (3 * HID);
            const float* wrow = w_ih + (size_t)u * HID;
            const float* erow = embed + (size_t)v * HID;
            float a = 0.0f;
            #pragma unroll
            for (int m = 0; m < 4; ++m) {
                int c = base + m * 128;
                float4 w4 = *(const float4*)(wrow + c);
                float4 e4 = *(const float4*)(erow + c);
                a = fmaf(w4.x, e4.x, fmaf(w4.y, e4.y, fmaf(w4.z, e4.z, fmaf(w4.w, e4.w, a))));
            }
            a = warp_allsum(a);
            if (lane == 0) g_gx[v][u] = a + b_ih[u];
        }
    }
    int eos_step = MAXLEN;   // meaningful on blk0/tid0

    grid_barrier();

    // row partition: blocks 0..31 (gh duty) get 100 rows; 32..147 get 113/114
    int t0, t1;
    if (blk < 32) { t0 = blk * 100; t1 = t0 + 100; }
    else {
        int b = blk - 32;
        int extra = b < 76 ? b : 76;
        t0 = 3200 + b * 113 + extra;
        t1 = t0 + 113 + (b < 76 ? 1 : 0);
    }
    const float scale = 0.04419417382415922f;   // 1/sqrt(512)

    for (int k = 0; k <= MAXLEN; ++k) {
        // ============ Phase A: epilogue of step k-1 (redundant per block) + GRU ============
        if (k > 0) {
            const int p = (k - 1) % NBUF;
            const float inv_total = 1.0f / g_tot[p];

            // attention output for step k-1 (from local s_exp)
            for (int t = t0 + tid; t < t1; t += NTHR)
                out_attn[(size_t)(k - 1) * TENC + t] = s_exp[t - t0] * inv_total;

            // concat [summary | h_k]
            s_cat[tid]       = g_sumv[p][tid] * inv_total;
            s_cat[HID + tid] = s_hh[tid];

            // zero buffer (k+1)%3 for reuse at B(k+2)
            if (blk == 0) {
                const int zb = (k + 1) % NBUF;
                g_sumv[zb][tid] = 0.0f;
                if (tid == 0) g_tot[zb] = 0.0f;
            }
            __syncthreads();

            // logits from smem w_out (identical in every block)
            for (int v = wid; v < NVOCAB; v += NW) {
                const float* wrow = s_wout + v * (2 * HID);
                float dot = 0.0f;
                #pragma unroll
                for (int m = 0; m < 8; ++m) {
                    int c = base + m * 128;
                    float4 w4 = *(const float4*)(wrow + c);
                    float4 x4 = *(const float4*)(s_cat + c);
                    dot = fmaf(w4.x, x4.x, fmaf(w4.y, x4.y, fmaf(w4.z, x4.z, fmaf(w4.w, x4.w, dot))));
                }
                dot = warp_allsum(dot);
                if (lane == 0) {
                    dot += b_out[v];
                    s_logit[v] = dot;
                    if (blk == 0) out_logits[(k - 1) * NVOCAB + v] = dot;
                }
            }
            __syncthreads();
            if (tid == 0) {
                int best = 0; float bv = s_logit[0];
                #pragma unroll
                for (int v = 1; v < NVOCAB; ++v)
                    if (s_logit[v] > bv) { bv = s_logit[v]; best = v; }
                s_best = best;
                if (blk == 0 && best == EOSI && eos_step == MAXLEN) eos_step = k - 1;
            }
            __syncthreads();
        }

        if (k == MAXLEN) break;

        // GRU pointwise: h_{k+1} = GRU(gx[best], gh_k, h_k)   (j = tid)
        {
            const float* gx = g_gx[s_best];
            const int pg = k & 1;
            float r = 1.0f / (1.0f + __expf(-(gx[tid]             + g_gh[pg][0][tid])));
            float z = 1.0f / (1.0f + __expf(-(gx[tid + HID]       + g_gh[pg][1][tid])));
            float n = tanhf(gx[tid + 2 * HID] + r * g_gh[pg][2][tid]);
            s_hh[tid] = (1.0f - z) * n + z * s_hh[tid];
        }
        __syncthreads();

        // ============ Phase B: attention sweep (+ gh for next step on blocks 0-31) ============
        s_acc[tid] = 0.0f;
        // hoist h into registers (16 per lane: columns base+{0..3}+128m)
        float4 h0 = *(const float4*)(s_hh + base);
        float4 h1 = *(const float4*)(s_hh + base + 128);
        float4 h2 = *(const float4*)(s_hh + base + 256);
        float4 h3 = *(const float4*)(s_hh + base + 384);
        __syncthreads();

        float4 acc0 = {0,0,0,0}, acc1 = {0,0,0,0}, acc2 = {0,0,0,0}, acc3 = {0,0,0,0};
        float esum = 0.0f;

        for (int tb = t0 + wid; tb < t1; tb += NW * 4) {
            float dotv[4];
            int   okv[4];
            int   trv[4];
            // pass 1: keys -> dots (16 loads in flight)
            #pragma unroll
            for (int r = 0; r < 4; ++r) {
                int t = tb + r * NW;
                trv[r] = (t < t1) ? t : t0;
                const float* row = enc + (size_t)trv[r] * (2 * HID);
                float4 k0 = __ldcg((const float4*)(row + base));
                float4 k1 = __ldcg((const float4*)(row + base + 128));
                float4 k2 = __ldcg((const float4*)(row + base + 256));
                float4 k3 = __ldcg((const float4*)(row + base + 384));
                float d = 0.0f;
                d = fmaf(k0.x, h0.x, fmaf(k0.y, h0.y, fmaf(k0.z, h0.z, fmaf(k0.w, h0.w, d))));
                d = fmaf(k1.x, h1.x, fmaf(k1.y, h1.y, fmaf(k1.z, h1.z, fmaf(k1.w, h1.w, d))));
                d = fmaf(k2.x, h2.x, fmaf(k2.y, h2.y, fmaf(k2.z, h2.z, fmaf(k2.w, h2.w, d))));
                d = fmaf(k3.x, h3.x, fmaf(k3.y, h3.y, fmaf(k3.z, h3.z, fmaf(k3.w, h3.w, d))));
                dotv[r] = d;
                int ok = (k0.x != PADV) | (k0.y != PADV) | (k0.z != PADV) | (k0.w != PADV)
                       | (k1.x != PADV) | (k1.y != PADV) | (k1.z != PADV) | (k1.w != PADV)
                       | (k2.x != PADV) | (k2.y != PADV) | (k2.z != PADV) | (k2.w != PADV)
                       | (k3.x != PADV) | (k3.y != PADV) | (k3.z != PADV) | (k3.w != PADV);
                okv[r] = ok;
            }
            // pipelined reductions
            #pragma unroll
            for (int r = 0; r < 4; ++r) dotv[r] = warp_allsum(dotv[r]);
            float ev[4];
            #pragma unroll
            for (int r = 0; r < 4; ++r) {
                int t = tb + r * NW;
                int ok = __any_sync(0xffffffffu, okv[r]);
                float e = (t < t1 && ok) ? __expf(dotv[r] * scale) : 0.0f;
                ev[r] = e;
                if (lane == 0 && t < t1) s_exp[t - t0] = e;
                esum += e;
            }
            // pass 2: values
            #pragma unroll
            for (int r = 0; r < 4; ++r) {
                const float* row = enc + (size_t)trv[r] * (2 * HID) + HID;
                float4 v0 = __ldcg((const float4*)(row + base));
                float4 v1 = __ldcg((const float4*)(row + base + 128));
                float4 v2 = __ldcg((const float4*)(row + base + 256));
                float4 v3 = __ldcg((const float4*)(row + base + 384));
                float e = ev[r];
                acc0.x = fmaf(e, v0.x, acc0.x); acc0.y = fmaf(e, v0.y, acc0.y);
                acc0.z = fmaf(e, v0.z, acc0.z); acc0.w = fmaf(e, v0.w, acc0.w);
                acc1.x = fmaf(e, v1.x, acc1.x); acc1.y = fmaf(e, v1.y, acc1.y);
                acc1.z = fmaf(e, v1.z, acc1.z); acc1.w = fmaf(e, v1.w, acc1.w);
                acc2.x = fmaf(e, v2.x, acc2.x); acc2.y = fmaf(e, v2.y, acc2.y);
                acc2.z = fmaf(e, v2.z, acc2.z); acc2.w = fmaf(e, v2.w, acc2.w);
                acc3.x = fmaf(e, v3.x, acc3.x); acc3.y = fmaf(e, v3.y, acc3.y);
                acc3.z = fmaf(e, v3.z, acc3.z); acc3.w = fmaf(e, v3.w, acc3.w);
            }
        }

        // gh precompute for step k+1 (blocks 0-31, one warp per hidden unit)
        if (blk < 32) {
            const int j = blk * NW + wid;
            const int pn = (k + 1) & 1;
            const float* ur = w_hh + (size_t)j * HID;
            const float* uz = ur + (size_t)HID * HID;
            const float* un = uz + (size_t)HID * HID;
            float a3 = 0, a4 = 0, a5 = 0;
            #pragma unroll
            for (int m = 0; m < 4; ++m) {
                int c = base + m * 128;
                float4 hx; hx.x = s_hh[c]; hx.y = s_hh[c+1]; hx.z = s_hh[c+2]; hx.w = s_hh[c+3];
                float4 u0 = *(const float4*)(ur + c);
                float4 u1 = *(const float4*)(uz + c);
                float4 u2 = *(const float4*)(un + c);
                a3 = fmaf(hx.x, u0.x, fmaf(hx.y, u0.y, fmaf(hx.z, u0.z, fmaf(hx.w, u0.w, a3))));
                a4 = fmaf(hx.x, u1.x, fmaf(hx.y, u1.y, fmaf(hx.z, u1.z, fmaf(hx.w, u1.w, a4))));
                a5 = fmaf(hx.x, u2.x, fmaf(hx.y, u2.y, fmaf(hx.z, u2.z, fmaf(hx.w, u2.w, a5))));
            }
            a3 = warp_allsum(a3); a4 = warp_allsum(a4); a5 = warp_allsum(a5);
            if (lane == 0) {
                g_gh[pn][0][j] = a3 + b_hh[j];
                g_gh[pn][1][j] = a4 + b_hh[j + HID];
                g_gh[pn][2][j] = a5 + b_hh[j + 2 * HID];
            }
        }

        // merge per-thread accumulators -> block -> global (buffer k%3)
        const int bb = k % NBUF;
        atomicAdd(&s_acc[base + 0],       acc0.x); atomicAdd(&s_acc[base + 1],       acc0.y);
        atomicAdd(&s_acc[base + 2],       acc0.z); atomicAdd(&s_acc[base + 3],       acc0.w);
        atomicAdd(&s_acc[base + 128 + 0], acc1.x); atomicAdd(&s_acc[base + 128 + 1], acc1.y);
        atomicAdd(&s_acc[base + 128 + 2], acc1.z); atomicAdd(&s_acc[base + 128 + 3], acc1.w);
        atomicAdd(&s_acc[base + 256 + 0], acc2.x); atomicAdd(&s_acc[base + 256 + 1], acc2.y);
        atomicAdd(&s_acc[base + 256 + 2], acc2.z); atomicAdd(&s_acc[base + 256 + 3], acc2.w);
        atomicAdd(&s_acc[base + 384 + 0], acc3.x); atomicAdd(&s_acc[base + 384 + 1], acc3.y);
        atomicAdd(&s_acc[base + 384 + 2], acc3.z); atomicAdd(&s_acc[base + 384 + 3], acc3.w);
        if (lane == 0) s_red[wid] = esum;
        __syncthreads();
        if (tid == 0) {
            float tot = 0.0f;
            #pragma unroll
            for (int w = 0; w < NW; ++w) tot += s_red[w];
            atomicAdd(&g_tot[bb], tot);
        }
        atomicAdd(&g_sumv[bb][tid], s_acc[tid]);

        grid_barrier();   // the ONE barrier per step
    }

    if (blk == 0 && tid == 0) out_len[0] = (float)eos_step;
}

extern "C" void kernel_launch(void* const* d_in, const int* in_sizes, int n_in,
                              void* d_out, int out_size) {
    const float* enc   = (const float*)d_in[0];   // encoding [1,16384,1024]
    const float* embed = (const float*)d_in[2];
    const float* w_ih  = (const float*)d_in[3];
    const float* w_hh  = (const float*)d_in[4];
    const float* b_ih  = (const float*)d_in[5];
    const float* b_hh  = (const float*)d_in[6];
    const float* w_out = (const float*)d_in[7];
    const float* b_out = (const float*)d_in[8];
    (void)in_sizes; (void)n_in; (void)out_size;

    const int smem_dyn = NVOCAB * 2 * HID * sizeof(float);   // 126976 B
    static int attr_set = 0;
    if (!attr_set) {
        cudaFuncSetAttribute(decoder_kernel,
                             cudaFuncAttributeMaxDynamicSharedMemorySize, smem_dyn);
        attr_set = 1;
    }
    decoder_kernel<<<NBLK, NTHR, smem_dyn>>>(enc, embed, w_ih, w_hh, b_ih, b_hh,
                                             w_out, b_out, (float*)d_out);
}

// round 4
// speedup vs baseline: 1.9428x; 1.2038x over previous
#include <cuda_runtime.h>
#include <math.h>

#define NTHR   512
#define NW     (NTHR / 32)        // 16 warps
#define HID    512
#define TENC   16384
#define NVOCAB 31
#define MAXLEN 100
#define EOSI   29
#define PADV   30.0f
#define NBUF   3
#define MAXBLK 256

// ---------------- device scratch ----------------
__device__ __align__(16) float g_sumv[NBUF][HID];     // attention summary accumulators
__device__ float g_tot[NBUF];                         // softmax denominators
__device__ __align__(16) float g_gh[2][3][HID];       // w_hh@h + b_hh (r,z,n), double buffered
__device__ __align__(16) float g_gx[NVOCAB][3 * HID]; // w_ih@embed[v] + b_ih
__device__ volatile int g_arrive[MAXBLK];
__device__ volatile int g_release;

__device__ __forceinline__ float warp_allsum(float v) {
    #pragma unroll
    for (int o = 16; o; o >>= 1) v += __shfl_xor_sync(0xffffffffu, v, o);
    return v;
}

extern __shared__ float s_wout[];   // [31][1024] copy of w_out

__global__ void __launch_bounds__(NTHR, 1)
decoder_kernel(const float* __restrict__ enc,     // [TENC, 1024] keys|values
               const float* __restrict__ embed,   // [31, 512]
               const float* __restrict__ w_ih,    // [1536, 512]
               const float* __restrict__ w_hh,    // [1536, 512]
               const float* __restrict__ b_ih,    // [1536]
               const float* __restrict__ b_hh,    // [1536]
               const float* __restrict__ w_out,   // [31, 1024]
               const float* __restrict__ b_out,   // [31]
               float* __restrict__ out)
{
    const int tid  = threadIdx.x;
    const int blk  = blockIdx.x;
    const int nblk = gridDim.x;
    const int wid  = tid >> 5;
    const int lane = tid & 31;
    const int base = lane * 4;

    __shared__ __align__(16) float s_hh[HID];          // h (per-block copy)
    __shared__ __align__(16) float s_sum[HID];         // normalized summary
    __shared__ __align__(16) float s_warp[NW][HID];    // per-warp value accumulators
    __shared__ float s_exp[128];
    __shared__ float s_lh[NVOCAB];                     // w_out_h . h + b_out
    __shared__ float s_logit[NVOCAB];
    __shared__ float s_red[NW];
    __shared__ int   s_best;

    float* out_logits = out;                        // [100, 31]
    float* out_len    = out + MAXLEN * NVOCAB;      // [1]
    float* out_attn   = out + MAXLEN * NVOCAB + 1;  // [100, 16384]

    int ep = g_release;

    auto grid_barrier = [&]() {
        ep++;
        __syncthreads();
        __threadfence();
        if (blk == 0) {
            for (int i = tid; i < nblk; i += NTHR)
                if (i > 0) { while (g_arrive[i] < ep) { } }
            __threadfence();
            __syncthreads();
            if (tid == 0) g_release = ep;
        } else {
            if (tid == 0) {
                g_arrive[blk] = ep;
                while (g_release < ep) { }
                __threadfence();
            }
        }
        __syncthreads();
    };

    // ---------------- per-launch init ----------------
    s_hh[tid] = 0.0f;                     // h0 = 0   (NTHR == HID)
    if (tid == 0) s_best = EOSI;          // y0 = embed[EOS]
    for (int i = tid; i < NVOCAB * 2 * HID; i += NTHR) s_wout[i] = w_out[i];
    if (blk == 0) {
        #pragma unroll
        for (int b = 0; b < NBUF; ++b) g_sumv[b][tid] = 0.0f;
        g_gh[0][0][tid] = b_hh[tid];
        g_gh[0][1][tid] = b_hh[tid + HID];
        g_gh[0][2][tid] = b_hh[tid + 2 * HID];
        if (tid == 0) { g_tot[0] = 0.0f; g_tot[1] = 0.0f; g_tot[2] = 0.0f; }
    }
    // gx table: gx[v][u] = w_ih[u] . embed[v] + b_ih[u]
    {
        const int gw = blk * NW + wid;
        for (int r = gw; r < NVOCAB * 3 * HID; r += nblk * NW) {
            const int v = r / (3 * HID);
            const int u = r - v * (3 * HID);
            const float* wrow = w_ih + (size_t)u * HID;
            const float* erow = embed + (size_t)v * HID;
            float a = 0.0f;
            #pragma unroll
            for (int m = 0; m < 4; ++m) {
                int c = base + m * 128;
                float4 w4 = *(const float4*)(wrow + c);
                float4 e4 = *(const float4*)(erow + c);
                a = fmaf(w4.x, e4.x, fmaf(w4.y, e4.y, fmaf(w4.z, e4.z, fmaf(w4.w, e4.w, a))));
            }
            a = warp_allsum(a);
            if (lane == 0) g_gx[v][u] = a + b_ih[u];
        }
    }
    // first-step lh: uses h=0 -> lh[v] = b_out[v]
    if (tid < NVOCAB) s_lh[tid] = b_out[tid];
    int eos_step = MAXLEN;

    grid_barrier();

    // row partition: blocks 0..31 (gh duty) get `light`, rest `heavy`=light+13
    const int heavy = (TENC + 13 * 32 + nblk - 1) / nblk;
    const int light = heavy - 13;
    int t0 = (blk < 32) ? blk * light : 32 * light + (blk - 32) * heavy;
    int t1 = t0 + ((blk < 32) ? light : heavy);
    if (t0 > TENC) t0 = TENC;
    if (t1 > TENC) t1 = TENC;

    const float scale = 0.04419417382415922f;   // 1/sqrt(512)

    for (int k = 0; k <= MAXLEN; ++k) {
        // ============ Phase A: epilogue of step k-1 (redundant per block) ============
        if (k > 0) {
            const int p = (k - 1) % NBUF;
            const float inv_total = 1.0f / g_tot[p];

            for (int t = t0 + tid; t < t1; t += NTHR)
                out_attn[(size_t)(k - 1) * TENC + t] = s_exp[t - t0] * inv_total;

            s_sum[tid] = g_sumv[p][tid] * inv_total;

            if (blk == 0) {                       // zero buffer (k+1)%3 for B(k+1... reuse)
                const int zb = (k + 1) % NBUF;
                g_sumv[zb][tid] = 0.0f;
                if (tid == 0) g_tot[zb] = 0.0f;
            }
            __syncthreads();

            // logits: summary half from smem w_out; h half precomputed in s_lh
            for (int v = wid; v < NVOCAB; v += NW) {
                const float* wrow = s_wout + v * (2 * HID);
                float dot = 0.0f;
                #pragma unroll
                for (int m = 0; m < 4; ++m) {
                    int c = base + m * 128;
                    float4 w4 = *(const float4*)(wrow + c);
                    float4 x4 = *(const float4*)(s_sum + c);
                    dot = fmaf(w4.x, x4.x, fmaf(w4.y, x4.y, fmaf(w4.z, x4.z, fmaf(w4.w, x4.w, dot))));
                }
                dot = warp_allsum(dot);
                if (lane == 0) {
                    dot += s_lh[v];
                    s_logit[v] = dot;
                    if (blk == 0) out_logits[(k - 1) * NVOCAB + v] = dot;
                }
            }
            __syncthreads();
            if (tid == 0) {
                int best = 0; float bv = s_logit[0];
                #pragma unroll
                for (int v = 1; v < NVOCAB; ++v)
                    if (s_logit[v] > bv) { bv = s_logit[v]; best = v; }
                s_best = best;
                if (blk == 0 && best == EOSI && eos_step == MAXLEN) eos_step = k - 1;
            }
            __syncthreads();
        }

        if (k == MAXLEN) break;

        // GRU pointwise: h^{(k)} = GRU(gx[best], gh, h^{(k-1)})
        {
            const float* gx = g_gx[s_best];
            const int pg = k & 1;
            float r = 1.0f / (1.0f + __expf(-(gx[tid]             + g_gh[pg][0][tid])));
            float z = 1.0f / (1.0f + __expf(-(gx[tid + HID]       + g_gh[pg][1][tid])));
            float n = tanhf(gx[tid + 2 * HID] + r * g_gh[pg][2][tid]);
            s_hh[tid] = (1.0f - z) * n + z * s_hh[tid];
        }
        __syncthreads();

        // ============ Phase B: attention sweep ============
        float4 h0 = *(const float4*)(s_hh + base);
        float4 h1 = *(const float4*)(s_hh + base + 128);
        float4 h2 = *(const float4*)(s_hh + base + 256);
        float4 h3 = *(const float4*)(s_hh + base + 384);

        float4 acc0 = {0,0,0,0}, acc1 = {0,0,0,0}, acc2 = {0,0,0,0}, acc3 = {0,0,0,0};
        float esum = 0.0f;

        for (int ta = t0 + wid; ta < t1; ta += NW * 2) {
            const int tb   = ta + NW;
            const int bok  = (tb < t1);
            const int trb  = bok ? tb : ta;
            const float* ra = enc + (size_t)ta  * (2 * HID);
            const float* rb = enc + (size_t)trb * (2 * HID);
            // load keys+values for both rows (16 LDG.128 in flight)
            float4 ka0 = __ldcg((const float4*)(ra + base));
            float4 ka1 = __ldcg((const float4*)(ra + base + 128));
            float4 ka2 = __ldcg((const float4*)(ra + base + 256));
            float4 ka3 = __ldcg((const float4*)(ra + base + 384));
            float4 va0 = __ldcg((const float4*)(ra + HID + base));
            float4 va1 = __ldcg((const float4*)(ra + HID + base + 128));
            float4 va2 = __ldcg((const float4*)(ra + HID + base + 256));
            float4 va3 = __ldcg((const float4*)(ra + HID + base + 384));
            float4 kb0 = __ldcg((const float4*)(rb + base));
            float4 kb1 = __ldcg((const float4*)(rb + base + 128));
            float4 kb2 = __ldcg((const float4*)(rb + base + 256));
            float4 kb3 = __ldcg((const float4*)(rb + base + 384));
            float4 vb0 = __ldcg((const float4*)(rb + HID + base));
            float4 vb1 = __ldcg((const float4*)(rb + HID + base + 128));
            float4 vb2 = __ldcg((const float4*)(rb + HID + base + 256));
            float4 vb3 = __ldcg((const float4*)(rb + HID + base + 384));

            float da = 0.0f, db = 0.0f;
            da = fmaf(ka0.x, h0.x, fmaf(ka0.y, h0.y, fmaf(ka0.z, h0.z, fmaf(ka0.w, h0.w, da))));
            da = fmaf(ka1.x, h1.x, fmaf(ka1.y, h1.y, fmaf(ka1.z, h1.z, fmaf(ka1.w, h1.w, da))));
            da = fmaf(ka2.x, h2.x, fmaf(ka2.y, h2.y, fmaf(ka2.z, h2.z, fmaf(ka2.w, h2.w, da))));
            da = fmaf(ka3.x, h3.x, fmaf(ka3.y, h3.y, fmaf(ka3.z, h3.z, fmaf(ka3.w, h3.w, da))));
            db = fmaf(kb0.x, h0.x, fmaf(kb0.y, h0.y, fmaf(kb0.z, h0.z, fmaf(kb0.w, h0.w, db))));
            db = fmaf(kb1.x, h1.x, fmaf(kb1.y, h1.y, fmaf(kb1.z, h1.z, fmaf(kb1.w, h1.w, db))));
            db = fmaf(kb2.x, h2.x, fmaf(kb2.y, h2.y, fmaf(kb2.z, h2.z, fmaf(kb2.w, h2.w, db))));
            db = fmaf(kb3.x, h3.x, fmaf(kb3.y, h3.y, fmaf(kb3.z, h3.z, fmaf(kb3.w, h3.w, db))));

            int oka = (ka0.x != PADV) | (ka0.y != PADV) | (ka0.z != PADV) | (ka0.w != PADV)
                    | (ka1.x != PADV) | (ka1.y != PADV) | (ka1.z != PADV) | (ka1.w != PADV)
                    | (ka2.x != PADV) | (ka2.y != PADV) | (ka2.z != PADV) | (ka2.w != PADV)
                    | (ka3.x != PADV) | (ka3.y != PADV) | (ka3.z != PADV) | (ka3.w != PADV);
            int okb = (kb0.x != PADV) | (kb0.y != PADV) | (kb0.z != PADV) | (kb0.w != PADV)
                    | (kb1.x != PADV) | (kb1.y != PADV) | (kb1.z != PADV) | (kb1.w != PADV)
                    | (kb2.x != PADV) | (kb2.y != PADV) | (kb2.z != PADV) | (kb2.w != PADV)
                    | (kb3.x != PADV) | (kb3.y != PADV) | (kb3.z != PADV) | (kb3.w != PADV);

            da = warp_allsum(da);
            db = warp_allsum(db);
            oka = __any_sync(0xffffffffu, oka);
            okb = __any_sync(0xffffffffu, okb);
            float ea = oka ? __expf(da * scale) : 0.0f;
            float eb = (bok && okb) ? __expf(db * scale) : 0.0f;
            if (lane == 0) {
                s_exp[ta - t0] = ea;
                if (bok) s_exp[tb - t0] = eb;
                esum += ea + eb;
            }
            acc0.x = fmaf(ea, va0.x, fmaf(eb, vb0.x, acc0.x));
            acc0.y = fmaf(ea, va0.y, fmaf(eb, vb0.y, acc0.y));
            acc0.z = fmaf(ea, va0.z, fmaf(eb, vb0.z, acc0.z));
            acc0.w = fmaf(ea, va0.w, fmaf(eb, vb0.w, acc0.w));
            acc1.x = fmaf(ea, va1.x, fmaf(eb, vb1.x, acc1.x));
            acc1.y = fmaf(ea, va1.y, fmaf(eb, vb1.y, acc1.y));
            acc1.z = fmaf(ea, va1.z, fmaf(eb, vb1.z, acc1.z));
            acc1.w = fmaf(ea, va1.w, fmaf(eb, vb1.w, acc1.w));
            acc2.x = fmaf(ea, va2.x, fmaf(eb, vb2.x, acc2.x));
            acc2.y = fmaf(ea, va2.y, fmaf(eb, vb2.y, acc2.y));
            acc2.z = fmaf(ea, va2.z, fmaf(eb, vb2.z, acc2.z));
            acc2.w = fmaf(ea, va2.w, fmaf(eb, vb2.w, acc2.w));
            acc3.x = fmaf(ea, va3.x, fmaf(eb, vb3.x, acc3.x));
            acc3.y = fmaf(ea, va3.y, fmaf(eb, vb3.y, acc3.y));
            acc3.z = fmaf(ea, va3.z, fmaf(eb, vb3.z, acc3.z));
            acc3.w = fmaf(ea, va3.w, fmaf(eb, vb3.w, acc3.w));
        }

        // gh precompute for step k+1 (blocks 0-31, one warp per hidden unit)
        if (blk < 32) {
            const int j = blk * NW + wid;
            const int pn = (k + 1) & 1;
            const float* ur = w_hh + (size_t)j * HID;
            const float* uz = ur + (size_t)HID * HID;
            const float* un = uz + (size_t)HID * HID;
            float a3 = 0, a4 = 0, a5 = 0;
            #pragma unroll
            for (int m = 0; m < 4; ++m) {
                int c = base + m * 128;
                float4 hx = *(const float4*)(s_hh + c);
                float4 u0 = *(const float4*)(ur + c);
                float4 u1 = *(const float4*)(uz + c);
                float4 u2 = *(const float4*)(un + c);
                a3 = fmaf(hx.x, u0.x, fmaf(hx.y, u0.y, fmaf(hx.z, u0.z, fmaf(hx.w, u0.w, a3))));
                a4 = fmaf(hx.x, u1.x, fmaf(hx.y, u1.y, fmaf(hx.z, u1.z, fmaf(hx.w, u1.w, a4))));
                a5 = fmaf(hx.x, u2.x, fmaf(hx.y, u2.y, fmaf(hx.z, u2.z, fmaf(hx.w, u2.w, a5))));
            }
            a3 = warp_allsum(a3); a4 = warp_allsum(a4); a5 = warp_allsum(a5);
            if (lane == 0) {
                g_gh[pn][0][j] = a3 + b_hh[j];
                g_gh[pn][1][j] = a4 + b_hh[j + HID];
                g_gh[pn][2][j] = a5 + b_hh[j + 2 * HID];
            }
        }

        // lh for NEXT epilogue: lh[v] = w_out[v, 512:1024] . h^{(k)} + b_out[v]
        for (int v = wid; v < NVOCAB; v += NW) {
            const float* wrow = s_wout + v * (2 * HID) + HID;
            float dot = 0.0f;
            float4 w4;
            w4 = *(const float4*)(wrow + base);
            dot = fmaf(w4.x, h0.x, fmaf(w4.y, h0.y, fmaf(w4.z, h0.z, fmaf(w4.w, h0.w, dot))));
            w4 = *(const float4*)(wrow + base + 128);
            dot = fmaf(w4.x, h1.x, fmaf(w4.y, h1.y, fmaf(w4.z, h1.z, fmaf(w4.w, h1.w, dot))));
            w4 = *(const float4*)(wrow + base + 256);
            dot = fmaf(w4.x, h2.x, fmaf(w4.y, h2.y, fmaf(w4.z, h2.z, fmaf(w4.w, h2.w, dot))));
            w4 = *(const float4*)(wrow + base + 384);
            dot = fmaf(w4.x, h3.x, fmaf(w4.y, h3.y, fmaf(w4.z, h3.z, fmaf(w4.w, h3.w, dot))));
            dot = warp_allsum(dot);
            if (lane == 0) s_lh[v] = dot + b_out[v];
        }

        // merge: per-warp staging (no smem atomics) -> tree reduce -> 1 global atomic/thread
        *(float4*)&s_warp[wid][base]       = acc0;
        *(float4*)&s_warp[wid][base + 128] = acc1;
        *(float4*)&s_warp[wid][base + 256] = acc2;
        *(float4*)&s_warp[wid][base + 384] = acc3;
        if (lane == 0) s_red[wid] = esum;
        __syncthreads();

        const int bb = k % NBUF;
        float colsum = 0.0f;
        #pragma unroll
        for (int w = 0; w < NW; ++w) colsum += s_warp[w][tid];
        atomicAdd(&g_sumv[bb][tid], colsum);
        if (tid == 0) {
            float tot = 0.0f;
            #pragma unroll
            for (int w = 0; w < NW; ++w) tot += s_red[w];
            atomicAdd(&g_tot[bb], tot);
        }

        grid_barrier();   // the one barrier per step
    }

    if (blk == 0 && tid == 0) out_len[0] = (float)eos_step;
}

extern "C" void kernel_launch(void* const* d_in, const int* in_sizes, int n_in,
                              void* d_out, int out_size) {
    const float* enc   = (const float*)d_in[0];   // encoding [1,16384,1024]
    const float* embed = (const float*)d_in[2];
    const float* w_ih  = (const float*)d_in[3];
    const float* w_hh  = (const float*)d_in[4];
    const float* b_ih  = (const float*)d_in[5];
    const float* b_hh  = (const float*)d_in[6];
    const float* w_out = (const float*)d_in[7];
    const float* b_out = (const float*)d_in[8];
    (void)in_sizes; (void)n_in; (void)out_size;

    const int smem_dyn = NVOCAB * 2 * HID * sizeof(float);   // 126976 B
    static int nblk = 0;
    if (!nblk) {
        cudaFuncSetAttribute(decoder_kernel,
                             cudaFuncAttributeMaxDynamicSharedMemorySize, smem_dyn);
        int dev = 0;
        cudaGetDevice(&dev);
        int sms = 0;
        cudaDeviceGetAttribute(&sms, cudaDevAttrMultiProcessorCount, dev);
        nblk = (sms >= 64 && sms <= MAXBLK) ? sms : 148;
    }
    decoder_kernel<<<nblk, NTHR, smem_dyn>>>(enc, embed, w_ih, w_hh, b_ih, b_hh,
                                             w_out, b_out, (float*)d_out);
}